// round 3
// baseline (speedup 1.0000x reference)
#include <cuda_runtime.h>
#include <cstdint>

// Problem constants (fixed by the reference)
#define DD 64
#define HH 8
#define PP 4
#define EE 130              // 2*D + 2
#define NTOK 32768          // B*N = 8*4096
#define HE 1040             // H*E
#define TENSOR_ELEMS (NTOK * HE)   // 34,078,720 per output tensor

#define TT 64               // tokens per CTA tile
#define NTILES (NTOK / TT)  // 512
#define THREADS 256

#define MAT_STRIDE 4098     // 64*64 floats + 2-float pad (bank-parity stagger)
#define WSM_FLOATS (8 * MAT_STRIDE)          // 32784
#define XS_FLOATS (TT * 64)                  // 4096
#define SMEM_FLOATS (WSM_FLOATS + 2 * XS_FLOATS + 2 * TT)  // 41104
#define SMEM_BYTES (SMEM_FLOATS * 4)         // 164,416 B

__device__ __forceinline__ double fma2(double a, double b, double c) {
    double d;
    asm("fma.rn.f32x2 %0, %1, %2, %3;" : "=d"(d) : "d"(a), "d"(b), "d"(c));
    return d;
}

__device__ __forceinline__ float pair_sum(double a) {
    return __int_as_float(__double2loint(a)) + __int_as_float(__double2hiint(a));
}

__device__ __forceinline__ double pack2(float lo, float hi) {
    double d;
    asm("mov.b64 %0, {%1, %2};" : "=d"(d) : "f"(lo), "f"(hi));
    return d;
}

extern __shared__ float smem[];

__global__ __launch_bounds__(THREADS, 1)
void qkv_kernel(const float* __restrict__ x,
                const float* __restrict__ Mq,
                const float* __restrict__ Bq,
                const float* __restrict__ Mk,
                const float* __restrict__ Bk,
                const float* __restrict__ Mv,
                float* __restrict__ out)
{
    const int tile = blockIdx.x >> 1;
    const bool isV = (blockIdx.x & 1) != 0;
    const int tid  = threadIdx.x;
    const int tok0 = tile * TT;

    float* wsm   = smem;
    float* x1s   = smem + WSM_FLOATS;
    float* x2s   = x1s + XS_FLOATS;
    float* smid  = x2s + XS_FLOATS;
    float* slast = smid + TT;
    (void)smid; (void)slast;

    float* outQ = out;
    float* outK = out + (size_t)TENSOR_ELEMS;
    float* outV = out + (size_t)2 * TENSOR_ELEMS;

    // ---- Stage 8 weight matrices into smem (float4 loads, swizzled pairs) ----
    // QK CTA: mats 0..3 = M_q[0..3], mats 4..7 = M_k[0..3]
    // V  CTA: mats 0..7 = M_v[0..7]
    const float* srcA = isV ? Mv : Mq;              // mats 0..3
    const float* srcB = isV ? (Mv + 4 * 4096) : Mk; // mats 4..7
    for (int idx = tid; idx < 8 * 1024; idx += THREADS) {   // idx over float4s
        int mat = idx >> 10;
        int r4  = idx & 1023;          // float4 index within matrix
        int i   = r4 >> 4;             // row of M (output dim)
        int j4  = (r4 & 15) << 2;      // starting k (multiple of 4)
        const float4 v = (mat < 4)
            ? ((const float4*)(srcA + mat * 4096))[r4]
            : ((const float4*)(srcB + (mat - 4) * 4096))[r4];
        int kp0   = j4 >> 1;           // first k-pair (even)
        int rot   = 2 * (i & 7);
        int s0    = (kp0 + rot) & 31;
        int s1    = (kp0 + 1 + rot) & 31;
        double* row = (double*)(wsm + mat * MAT_STRIDE + i * 64);
        row[s0] = pack2(v.x, v.y);
        row[s1] = pack2(v.z, v.w);
    }

    // ---- Stage x tile into smem (x1, x2 aligned; scalars kept too) ----
    for (int idx = tid; idx < TT * EE; idx += THREADS) {
        int t = idx / EE;
        int e = idx - t * EE;
        float v = x[(size_t)(tok0 + t) * EE + e];
        if (e < 64)        x1s[t * 64 + e] = v;
        else if (e == 64)  smid[t] = v;
        else if (e < 129)  x2s[t * 64 + (e - 65)] = v;
        else               slast[t] = v;
    }

    // ---- Structural zeros + scalar outputs (disjoint from computed addrs) ----
    const int warp = tid >> 5, lane = tid & 31;
    if (!isV) {
        // q,k: every head zeroes [0,65)
        for (int r = warp; r < 1024; r += 8) {
            int tau = r >> 9;        // 0=q, 1=k
            int th  = r & 511;
            int t = th >> 3, h = th & 7;
            float* base = (tau ? outK : outQ) + (size_t)(tok0 + t) * HE + h * 130;
            base[lane] = 0.f; base[lane + 32] = 0.f;
            if (lane == 0) base[64] = 0.f;
        }
        // q,k heads 4..7: zero [66,130)
        for (int r = warp; r < 512; r += 8) {
            int tau = r >> 8;
            int th  = r & 255;
            int t = th >> 2, h = 4 + (th & 3);
            float* base = (tau ? outK : outQ) + (size_t)(tok0 + t) * HE + h * 130 + 66;
            base[lane] = 0.f; base[lane + 32] = 0.f;
        }
        // scalar outputs (x scalars re-read from global: L1/L2-resident)
        for (int r = tid; r < 1024; r += THREADS) {
            int tau = r >> 9;
            int th  = r & 511;
            int t = th >> 3, h = th & 7;
            const float* xr = x + (size_t)(tok0 + t) * EE;
            float s, bv; int pos;
            if (tau == 0) { bv = Bq[h]; s = xr[129]; pos = (h < 4) ? 129 : 65; }
            else {
                bv = Bk[h];
                if (h < 4) { s = xr[129]; pos = 129; }
                else       { s = xr[64];  pos = 65;  }
            }
            (tau ? outK : outQ)[(size_t)(tok0 + t) * HE + h * 130 + pos] = s * bv;
        }
    } else {
        // v: every head zeroes [0,65) and element 129
        for (int r = warp; r < 512; r += 8) {
            int t = r >> 3, h = r & 7;
            float* base = outV + (size_t)(tok0 + t) * HE + h * 130;
            base[lane] = 0.f; base[lane + 32] = 0.f;
            if (lane == 0) { base[64] = 0.f; base[129] = 0.f; }
        }
    }

    __syncthreads();

    // ---- Compute: 2 passes x 4 matrices; per-thread 8 tokens x 8 cols ----
    // Warp-uniform token group -> x loads are pure smem broadcasts.
    // Weight LDS.64 runs in two 16-lane phases (mi{0,1}, then mi{2,3});
    // slot rotation keeps each phase conflict-free at the crossbar floor.
    const int tokG   = tid >> 5;   // warp id = token group
    const int colG   = tid & 31;
    const int mi     = colG >> 3;  // matrix within pass (0..3)
    const int colSub = colG & 7;   // owns output cols colSub + 8j
    const int myTok0 = tokG * 8;

    #pragma unroll 1
    for (int p = 0; p < 2; ++p) {
        const float* xsrc  = (!isV && p == 0) ? x2s : x1s;  // q uses x2; k,v use x1
        const float* wbase = wsm + (p * 4 + mi) * MAT_STRIDE + colSub * 64;

        double acc[8][8];
        #pragma unroll
        for (int i = 0; i < 8; ++i)
            #pragma unroll
            for (int j = 0; j < 8; ++j)
                acc[i][j] = 0.0;

        #pragma unroll 4
        for (int kk = 0; kk < 32; ++kk) {
            const int slot = (kk + 2 * colSub) & 31;
            double xp[8], wp[8];
            #pragma unroll
            for (int i = 0; i < 8; ++i)
                xp[i] = *(const double*)&xsrc[(myTok0 + i) * 64 + 2 * kk];
            #pragma unroll
            for (int j = 0; j < 8; ++j)
                wp[j] = *(const double*)&wbase[j * 512 + slot * 2];
            #pragma unroll
            for (int i = 0; i < 8; ++i)
                #pragma unroll
                for (int j = 0; j < 8; ++j)
                    acc[i][j] = fma2(xp[i], wp[j], acc[i][j]);
        }

        float* tbase;
        int h;
        if (!isV) { tbase = p ? outK : outQ; h = mi; }
        else      { tbase = outV;            h = p * 4 + mi; }

        #pragma unroll
        for (int i = 0; i < 8; ++i) {
            float* o = tbase + (size_t)(tok0 + myTok0 + i) * HE + h * 130 + 65 + colSub;
            #pragma unroll
            for (int j = 0; j < 8; ++j)
                o[8 * j] = pair_sum(acc[i][j]);
        }
    }
}

extern "C" void kernel_launch(void* const* d_in, const int* in_sizes, int n_in,
                              void* d_out, int out_size) {
    const float* x  = (const float*)d_in[0];
    const float* Mq = (const float*)d_in[1];
    const float* Bq = (const float*)d_in[2];
    const float* Mk = (const float*)d_in[3];
    const float* Bk = (const float*)d_in[4];
    const float* Mv = (const float*)d_in[5];
    float* out = (float*)d_out;

    // Idempotent; not a stream op, so safe under graph capture. No static guard
    // (harness forbids call-count-dependent behavior).
    cudaFuncSetAttribute(qkv_kernel, cudaFuncAttributeMaxDynamicSharedMemorySize, SMEM_BYTES);
    qkv_kernel<<<2 * NTILES, THREADS, SMEM_BYTES>>>(x, Mq, Bq, Mk, Bk, Mv, out);
}

// round 4
// speedup vs baseline: 1.3445x; 1.3445x over previous
#include <cuda_runtime.h>
#include <cstdint>

// Problem constants
#define EE 130                     // 2*D + 2
#define HE 1040                    // H*E
#define NTOK 32768                 // B*N
#define TENSOR_ELEMS (NTOK * HE)

#define TT 32                      // tokens per CTA tile
#define NTILES (NTOK / TT)         // 1024
#define THREADS 256

#define MAT_STRIDE 4100            // 64*64 + 4 pad (keeps every matrix 16B-aligned)
#define WSM_FLOATS (4 * MAT_STRIDE)        // 16400
#define XS_FLOATS (TT * 64)                // 2048
#define SMEM_BYTES ((WSM_FLOATS + XS_FLOATS) * 4)   // 73,792 B -> 2 CTAs/SM

__device__ __forceinline__ double fma2(double a, double b, double c) {
    double d;
    asm("fma.rn.f32x2 %0, %1, %2, %3;" : "=d"(d) : "d"(a), "d"(b), "d"(c));
    return d;
}

__device__ __forceinline__ float pair_sum(double a) {
    return __int_as_float(__double2loint(a)) + __int_as_float(__double2hiint(a));
}

extern __shared__ float smem[];

// CTA types: 0=Q (M_q, x2), 1=K (M_k, x1), 2=V heads 0-3 (x1), 3=V heads 4-7 (x1)
__global__ __launch_bounds__(THREADS, 2)
void qkv_kernel(const float* __restrict__ x,
                const float* __restrict__ Mq,
                const float* __restrict__ Bq,
                const float* __restrict__ Mk,
                const float* __restrict__ Bk,
                const float* __restrict__ Mv,
                float* __restrict__ out)
{
    const int type = blockIdx.x & 3;
    const int tile = blockIdx.x >> 2;
    const int tok0 = tile * TT;
    const int tid  = threadIdx.x;

    float* wsm = smem;
    float* xs  = smem + WSM_FLOATS;

    float* outQ = out;
    float* outK = out + (size_t)TENSOR_ELEMS;
    float* outV = out + (size_t)2 * TENSOR_ELEMS;

    // ---- Stage 4 weight matrices (float4 LDG -> swizzled float4 STS) ----
    const float* wsrc = (type == 0) ? Mq
                      : (type == 1) ? Mk
                      : (type == 2) ? Mv
                      :               (Mv + 4 * 4096);
    for (int idx = tid; idx < 4 * 1024; idx += THREADS) {
        int mat = idx >> 10;
        int r4  = idx & 1023;
        int i   = r4 >> 4;             // output-dim row of M (= compute "col")
        int kp0 = (r4 & 15) * 2;       // first k-pair in this float4 (even)
        float4 v = ((const float4*)(wsrc + mat * 4096))[r4];
        int s0 = (kp0 + 2 * (i & 7)) & 31;   // even -> float4-aligned, no wrap
        *(float4*)(wsm + mat * MAT_STRIDE + i * 64 + s0 * 2) = v;
    }

    // ---- Stage x slice for this CTA type (Q uses x2 = x[65:129], else x1) ----
    const int xoff = (type == 0) ? 65 : 0;
    for (int idx = tid; idx < TT * 64; idx += THREADS) {
        int t = idx >> 6, e = idx & 63;
        xs[idx] = x[(size_t)(tok0 + t) * EE + xoff + e];
    }

    // ---- Structural zeros + scalar outputs (disjoint from computed addrs) ----
    const int warp = tid >> 5, lane = tid & 31;
    if (type < 2) {
        float* T = type ? outK : outQ;
        // every head: zero [0,65)
        for (int r = warp; r < 256; r += 8) {
            int t = r >> 3, h = r & 7;
            float* base = T + (size_t)(tok0 + t) * HE + h * 130;
            base[lane] = 0.f; base[lane + 32] = 0.f;
            if (lane == 0) base[64] = 0.f;
        }
        // heads 4-7: zero [66,130)
        for (int r = warp; r < 128; r += 8) {
            int t = r >> 2, h = 4 + (r & 3);
            float* base = T + (size_t)(tok0 + t) * HE + h * 130 + 66;
            base[lane] = 0.f; base[lane + 32] = 0.f;
        }
        // scalar outputs
        for (int r = tid; r < 256; r += THREADS) {
            int t = r >> 3, h = r & 7;
            const float* xr = x + (size_t)(tok0 + t) * EE;
            float s, bv; int pos;
            if (type == 0) { bv = Bq[h]; s = xr[129]; pos = (h < 4) ? 129 : 65; }
            else {
                bv = Bk[h];
                if (h < 4) { s = xr[129]; pos = 129; }
                else       { s = xr[64];  pos = 65;  }
            }
            T[(size_t)(tok0 + t) * HE + h * 130 + pos] = s * bv;
        }
    } else {
        // v: this CTA's 4 heads zero [0,65) and {129}
        int h0 = (type == 2) ? 0 : 4;
        for (int r = warp; r < 128; r += 8) {
            int t = r >> 2, h = h0 + (r & 3);
            float* base = outV + (size_t)(tok0 + t) * HE + h * 130;
            base[lane] = 0.f; base[lane + 32] = 0.f;
            if (lane == 0) { base[64] = 0.f; base[129] = 0.f; }
        }
    }

    __syncthreads();

    // ---- Compute: per-thread 8 tokens x 4 cols, 2 k-pairs per iteration ----
    // 8 warps: tokG = warp>>1 (8-token group), half = warp&1 (column half).
    // Lanes: mi = matrix (0..3), colSub = column subgroup; the slot rotation
    // makes each 8-lane LDS.128 phase hit all 32 banks exactly once.
    const int tokG   = warp >> 1;
    const int half   = warp & 1;
    const int mi     = lane >> 3;
    const int colSub = lane & 7;
    const int myTok0 = tokG * 8;

    const float* wrow0 = wsm + mi * MAT_STRIDE + (colSub + 32 * half) * 64;
    const float* xbase = xs + myTok0 * 64;

    double acc[8][4];
    #pragma unroll
    for (int i = 0; i < 8; ++i)
        #pragma unroll
        for (int j = 0; j < 4; ++j)
            acc[i][j] = 0.0;

    #pragma unroll 1
    for (int it = 0; it < 16; ++it) {
        const int s = (2 * it + 2 * colSub) & 31;   // even
        double2 xp[8], wp[4];
        #pragma unroll
        for (int i = 0; i < 8; ++i)                  // broadcast LDS.128
            xp[i] = *(const double2*)(xbase + i * 64 + 4 * it);
        #pragma unroll
        for (int j = 0; j < 4; ++j)                  // conflict-free LDS.128
            wp[j] = *(const double2*)(wrow0 + j * 512 + s * 2);
        #pragma unroll
        for (int i = 0; i < 8; ++i)
            #pragma unroll
            for (int j = 0; j < 4; ++j) {
                acc[i][j] = fma2(xp[i].x, wp[j].x, acc[i][j]);
                acc[i][j] = fma2(xp[i].y, wp[j].y, acc[i][j]);
            }
    }

    // ---- Epilogue: computed outputs ----
    float* T;
    int h;
    if (type == 0)      { T = outQ; h = mi; }
    else if (type == 1) { T = outK; h = mi; }
    else                { T = outV; h = ((type == 2) ? 0 : 4) + mi; }

    #pragma unroll
    for (int i = 0; i < 8; ++i) {
        float* o = T + (size_t)(tok0 + myTok0 + i) * HE + h * 130 + 65 + 32 * half + colSub;
        #pragma unroll
        for (int j = 0; j < 4; ++j)
            o[8 * j] = pair_sum(acc[i][j]);
    }
}

extern "C" void kernel_launch(void* const* d_in, const int* in_sizes, int n_in,
                              void* d_out, int out_size) {
    const float* x  = (const float*)d_in[0];
    const float* Mq = (const float*)d_in[1];
    const float* Bq = (const float*)d_in[2];
    const float* Mk = (const float*)d_in[3];
    const float* Bk = (const float*)d_in[4];
    const float* Mv = (const float*)d_in[5];
    float* out = (float*)d_out;

    cudaFuncSetAttribute(qkv_kernel, cudaFuncAttributeMaxDynamicSharedMemorySize, SMEM_BYTES);
    qkv_kernel<<<4 * NTILES, THREADS, SMEM_BYTES>>>(x, Mq, Bq, Mk, Bk, Mv, out);
}